// round 1
// baseline (speedup 1.0000x reference)
#include <cuda_runtime.h>

#define NTHREADS 1024
#define K_DET 100
#define NBINS 256
#define CAP 6144
#define M_TARGET 4096
#define NEGV (-1e10f)

__global__ __launch_bounds__(NTHREADS, 1)
void nms_kernel(const float* __restrict__ scores,
                const float* __restrict__ boxes,
                const int* __restrict__ classes,
                float* __restrict__ out,
                int B, int N) {
    extern __shared__ float sm[];
    float* sx1  = sm;
    float* sy1  = sx1 + CAP;
    float* sx2  = sy1 + CAP;
    float* sy2  = sx2 + CAP;
    float* ssc  = sy2 + CAP;
    int*   soi  = (int*)(ssc + CAP);
    int*   hist = soi + CAP;                    // NBINS ints
    float* stage = (float*)(hist + NBINS);      // K_DET*6 floats
    float* rs    = stage + K_DET * 6;           // 32
    int*   rslot = (int*)(rs + 32);             // 32
    int*   roi2  = rslot + 32;                  // 32

    __shared__ int s_cnt, s_tbin, s_selslot, s_seloi;
    __shared__ float s_sels;

    const int img = blockIdx.x;
    const int tid = threadIdx.x;
    const float* sc_in = scores + (size_t)img * N;
    const float* bx_in = boxes + (size_t)img * N * 4;

    // ---- Phase 1: histogram of scores above threshold ----
    for (int i = tid; i < NBINS; i += NTHREADS) hist[i] = 0;
    if (tid == 0) s_cnt = 0;
    __syncthreads();

    for (int i = tid; i < N; i += NTHREADS) {
        float s = sc_in[i];
        if (s > 0.05f) {
            int b = (int)(s * (float)NBINS);
            b = b < 0 ? 0 : (b > NBINS - 1 ? NBINS - 1 : b);
            atomicAdd(&hist[b], 1);
        }
    }
    __syncthreads();

    // ---- Phase 2: find threshold bin (top-down cumulative >= M_TARGET) ----
    if (tid == 0) {
        int cum = 0, b = NBINS - 1;
        for (; b > 0; --b) { cum += hist[b]; if (cum >= M_TARGET) break; }
        s_tbin = b;
    }
    __syncthreads();
    const int tb = s_tbin;

    // ---- Phase 3: warp-aggregated compaction of candidates into smem ----
    const int Npad = ((N + NTHREADS - 1) / NTHREADS) * NTHREADS;
    for (int i = tid; i < Npad; i += NTHREADS) {
        bool pass = false;
        float s = 0.f;
        if (i < N) {
            s = sc_in[i];
            if (s > 0.05f) {
                int b = (int)(s * (float)NBINS);
                b = b < 0 ? 0 : (b > NBINS - 1 ? NBINS - 1 : b);
                pass = (b >= tb);
            }
        }
        unsigned m = __ballot_sync(0xffffffffu, pass);
        int lane = tid & 31;
        int base = 0;
        if (lane == 0 && m) base = atomicAdd(&s_cnt, __popc(m));
        base = __shfl_sync(0xffffffffu, base, 0);
        if (pass) {
            int pos = base + __popc(m & ((1u << lane) - 1u));
            if (pos < CAP) {
                float4 bb = *reinterpret_cast<const float4*>(bx_in + (size_t)i * 4);
                sx1[pos] = bb.x; sy1[pos] = bb.y;
                sx2[pos] = bb.z; sy2[pos] = bb.w;
                ssc[pos] = s;    soi[pos] = i;
            }
        }
    }
    __syncthreads();
    const int C = min(s_cnt, CAP);

    // ---- Phase 4: greedy NMS over candidates (all in smem) ----
    int n_valid = 0;
    for (int it = 0; it < K_DET; ++it) {
        // block argmax with tie-break on lower original index (jnp.argmax semantics)
        float bs = -3.4e38f; int bslot = 0; int boi = 0x7fffffff;
        for (int j = tid; j < C; j += NTHREADS) {
            float s = ssc[j];
            int oi = soi[j];
            if (s > bs || (s == bs && oi < boi)) { bs = s; bslot = j; boi = oi; }
        }
        #pragma unroll
        for (int off = 16; off; off >>= 1) {
            float os  = __shfl_down_sync(0xffffffffu, bs, off);
            int oslot = __shfl_down_sync(0xffffffffu, bslot, off);
            int ooi   = __shfl_down_sync(0xffffffffu, boi, off);
            if (os > bs || (os == bs && ooi < boi)) { bs = os; bslot = oslot; boi = ooi; }
        }
        int wid = tid >> 5, lane = tid & 31;
        if (lane == 0) { rs[wid] = bs; rslot[wid] = bslot; roi2[wid] = boi; }
        __syncthreads();
        if (wid == 0) {
            bs = rs[lane]; bslot = rslot[lane]; boi = roi2[lane];
            #pragma unroll
            for (int off = 16; off; off >>= 1) {
                float os  = __shfl_down_sync(0xffffffffu, bs, off);
                int oslot = __shfl_down_sync(0xffffffffu, bslot, off);
                int ooi   = __shfl_down_sync(0xffffffffu, boi, off);
                if (os > bs || (os == bs && ooi < boi)) { bs = os; bslot = oslot; boi = ooi; }
            }
            if (lane == 0) { s_sels = bs; s_selslot = bslot; s_seloi = boi; }
        }
        __syncthreads();

        float sels = s_sels;
        bool valid = sels > -5e9f;   // matches: sc > NEG * 0.5
        if (valid) {
            int sl = s_selslot;
            float x1 = sx1[sl], y1 = sy1[sl], x2 = sx2[sl], y2 = sy2[sl];
            float areai = (x2 - x1) * (y2 - y1);
            for (int j = tid; j < C; j += NTHREADS) {
                float jx1 = sx1[j], jy1 = sy1[j], jx2 = sx2[j], jy2 = sy2[j];
                float xx1 = fmaxf(x1, jx1), yy1 = fmaxf(y1, jy1);
                float xx2 = fminf(x2, jx2), yy2 = fminf(y2, jy2);
                float inter = fmaxf(xx2 - xx1, 0.f) * fmaxf(yy2 - yy1, 0.f);
                float areaj = (jx2 - jx1) * (jy2 - jy1);
                float iou = inter / (areai + areaj - inter + 1e-6f);
                if (iou > 0.5f) ssc[j] = NEGV;
            }
            if (tid == 0) {
                ssc[sl] = NEGV;
                stage[it * 6 + 0] = (float)s_seloi;
                stage[it * 6 + 1] = sels;
                stage[it * 6 + 2] = x1;
                stage[it * 6 + 3] = y1;
                stage[it * 6 + 4] = x2;
                stage[it * 6 + 5] = y2;
                n_valid++;
            }
        } else {
            if (tid == 0) {
                stage[it * 6 + 0] = -1.f;
                stage[it * 6 + 1] = 0.f;
                stage[it * 6 + 2] = 0.f;
                stage[it * 6 + 3] = 0.f;
                stage[it * 6 + 4] = 0.f;
                stage[it * 6 + 5] = 0.f;
            }
        }
        __syncthreads();
    }

    // ---- Phase 5: write outputs (flattened tuple: idx, scores, boxes, classes, num_valid) ----
    const size_t BK = (size_t)B * K_DET;
    float* o_idx = out;
    float* o_sc  = out + BK;
    float* o_box = out + 2 * BK;
    float* o_cls = out + 6 * BK;
    float* o_nv  = out + 7 * BK;
    const int* cls_in = classes + (size_t)img * N;
    for (int t = tid; t < K_DET; t += NTHREADS) {
        float fi = stage[t * 6 + 0];
        size_t r = (size_t)img * K_DET + t;
        o_idx[r] = fi;
        o_sc[r]  = stage[t * 6 + 1];
        size_t bo = r * 4;
        o_box[bo + 0] = stage[t * 6 + 2];
        o_box[bo + 1] = stage[t * 6 + 3];
        o_box[bo + 2] = stage[t * 6 + 4];
        o_box[bo + 3] = stage[t * 6 + 5];
        o_cls[r] = (fi >= 0.f) ? (float)cls_in[(int)fi] : -1.f;
    }
    if (tid == 0) o_nv[img] = (float)n_valid;
}

extern "C" void kernel_launch(void* const* d_in, const int* in_sizes, int n_in,
                              void* d_out, int out_size) {
    const float* scores  = (const float*)d_in[0];
    const float* boxes   = (const float*)d_in[1];
    const int*   classes = (const int*)d_in[2];
    float* out = (float*)d_out;

    int B = out_size / (7 * K_DET + 1);   // 7*B*K + B elements
    if (B < 1) B = 1;
    int N = in_sizes[0] / B;

    size_t smem = (size_t)CAP * 6 * 4     // boxes SoA + score + idx
                + (size_t)NBINS * 4       // histogram
                + (size_t)K_DET * 6 * 4   // output staging
                + 32 * 4 * 3;             // reduction scratch

    cudaFuncSetAttribute(nms_kernel,
                         cudaFuncAttributeMaxDynamicSharedMemorySize,
                         (int)smem);

    nms_kernel<<<B, NTHREADS, smem>>>(scores, boxes, classes, out, B, N);
}

// round 2
// speedup vs baseline: 4.6140x; 4.6140x over previous
#include <cuda_runtime.h>
#include <cstdint>

#define NTHREADS 1024
#define K_DET 100
#define NBINS 256
#define CAP 6144
#define M_TARGET 4096
#define SORT_MAX 2048
#define CHUNK 128

__global__ __launch_bounds__(NTHREADS, 1)
void nms_kernel(const float* __restrict__ scores,
                const float* __restrict__ boxes,
                const int* __restrict__ classes,
                float* __restrict__ out, int B, int N) {
    extern __shared__ float4 smbase[];
    float4* sbox   = smbase;                                   // CAP
    float4* selbox = sbox + CAP;                               // K_DET
    unsigned long long* skey = (unsigned long long*)(selbox + K_DET); // SORT_MAX
    float* ssc     = (float*)(skey + SORT_MAX);                // CAP
    int*   soi     = (int*)(ssc + CAP);                        // CAP
    int*   kslot   = soi + CAP;                                // SORT_MAX
    int*   hist    = kslot + SORT_MAX;                         // NBINS
    int*   binstart= hist + NBINS;                             // NBINS
    int*   binpos  = binstart + NBINS;                         // NBINS
    float* selsc   = (float*)(binpos + NBINS);                 // K_DET
    int*   seloi   = (int*)(selsc + K_DET);                    // K_DET
    int*   presup  = seloi + K_DET;                            // CHUNK
    unsigned* supmask = (unsigned*)(presup + CHUNK);           // CHUNK*4

    __shared__ int s_tb, s_nsel;

    const int img = blockIdx.x;
    const int tid = threadIdx.x;
    const float* sc_in = scores + (size_t)img * N;
    const float* bx_in = boxes + (size_t)img * N * 4;

    // ---- Phase 1: 256-bin histogram of scores above threshold (float4 loads) ----
    for (int i = tid; i < NBINS; i += NTHREADS) hist[i] = 0;
    __syncthreads();

    const int n4 = N >> 2;
    const float4* sc4 = (const float4*)sc_in;
    for (int i = tid; i < n4; i += NTHREADS) {
        float4 v = sc4[i];
        if (v.x > 0.05f) atomicAdd(&hist[min((int)(v.x * 256.0f), 255)], 1);
        if (v.y > 0.05f) atomicAdd(&hist[min((int)(v.y * 256.0f), 255)], 1);
        if (v.z > 0.05f) atomicAdd(&hist[min((int)(v.z * 256.0f), 255)], 1);
        if (v.w > 0.05f) atomicAdd(&hist[min((int)(v.w * 256.0f), 255)], 1);
    }
    for (int i = (n4 << 2) + tid; i < N; i += NTHREADS) {
        float s = sc_in[i];
        if (s > 0.05f) atomicAdd(&hist[min((int)(s * 256.0f), 255)], 1);
    }
    __syncthreads();

    // ---- Phase 2: threshold bin + descending prefix offsets ----
    if (tid == 0) {
        int cum = 0, b = NBINS - 1;
        for (; b > 0; --b) { cum += hist[b]; if (cum >= M_TARGET) break; }
        s_tb = b;
        int run = 0;
        for (int x = NBINS - 1; x >= 0; --x) {
            binstart[x] = run; binpos[x] = run;
            if (x >= b) run += hist[x];
        }
        s_nsel = 0;
    }
    __syncthreads();
    const int tb = s_tb;

    // ---- Phase 3: counting-sort compaction by bin (descending bin order) ----
    for (int i = tid; i < N; i += NTHREADS) {
        float s = sc_in[i];
        if (s > 0.05f) {
            int b = min((int)(s * 256.0f), 255);
            if (b >= tb) {
                int pos = atomicAdd(&binpos[b], 1);
                if (pos < CAP) {
                    sbox[pos] = ((const float4*)bx_in)[i];
                    ssc[pos]  = s;
                    soi[pos]  = i;
                }
            }
        }
    }
    __syncthreads();

    // ---- Phase 4: sorted-walk greedy NMS, bin by bin (highest first) ----
    for (int b = NBINS - 1; b >= tb; --b) {
        int bs_ = binstart[b];
        int be_ = min(binpos[b], CAP);
        int cnt = be_ - bs_;
        if (cnt <= 0) continue;                 // uniform across block
        if (cnt > SORT_MAX) cnt = SORT_MAX;

        int P = 1; while (P < cnt) P <<= 1;
        if (P < 2) P = 1;

        // load sort keys: descending score, ascending original index
        for (int t = tid; t < P; t += NTHREADS) {
            if (t < cnt) {
                int sl = bs_ + t;
                unsigned sb = __float_as_uint(ssc[sl]);
                skey[t] = ((unsigned long long)(~sb) << 32) | (unsigned)soi[sl];
                kslot[t] = sl;
            } else {
                skey[t] = 0xFFFFFFFFFFFFFFFFULL;
                kslot[t] = -1;
            }
        }
        __syncthreads();

        // bitonic sort (ascending keys)
        for (int size = 2; size <= P; size <<= 1) {
            for (int stride = size >> 1; stride > 0; stride >>= 1) {
                int half = P >> 1;
                for (int t = tid; t < half; t += NTHREADS) {
                    int lo = ((t & ~(stride - 1)) << 1) | (t & (stride - 1));
                    int hi = lo + stride;
                    bool asc = ((lo & size) == 0);
                    unsigned long long a = skey[lo], c = skey[hi];
                    if ((a > c) == asc) {
                        skey[lo] = c; skey[hi] = a;
                        int tmp = kslot[lo]; kslot[lo] = kslot[hi]; kslot[hi] = tmp;
                    }
                }
                __syncthreads();
            }
        }

        // chunked walk
        int nch = (cnt + CHUNK - 1) / CHUNK;
        for (int ch = 0; ch < nch; ++ch) {
            int cb = ch * CHUNK;
            int cl = min(CHUNK, cnt - cb);

            if (tid < CHUNK) presup[tid] = 0;
            if (tid < CHUNK * 4) supmask[tid] = 0;
            __syncthreads();

            int ns = s_nsel;
            // pre-suppression: candidate c vs all currently-selected boxes
            {
                int c = tid >> 3, k = tid & 7;
                if (c < cl) {
                    float4 bc = sbox[kslot[cb + c]];
                    float areac = (bc.z - bc.x) * (bc.w - bc.y);
                    int hit = 0;
                    for (int s = k; s < ns; s += 8) {
                        float4 bsx = selbox[s];
                        float xx1 = fmaxf(bsx.x, bc.x), yy1 = fmaxf(bsx.y, bc.y);
                        float xx2 = fminf(bsx.z, bc.z), yy2 = fminf(bsx.w, bc.w);
                        float inter = fmaxf(xx2 - xx1, 0.f) * fmaxf(yy2 - yy1, 0.f);
                        float areas_ = (bsx.z - bsx.x) * (bsx.w - bsx.y);
                        float iou = inter / (areas_ + areac - inter + 1e-6f);
                        if (iou > 0.5f) { hit = 1; break; }
                    }
                    if (hit) presup[c] = 1;
                }
            }
            // intra-chunk pairwise suppression mask: i (earlier) suppresses j
            {
                int j = tid >> 3, k = tid & 7;
                if (j > 0 && j < cl) {
                    float4 bj = sbox[kslot[cb + j]];
                    float areaj = (bj.z - bj.x) * (bj.w - bj.y);
                    for (int i = k; i < j; i += 8) {
                        float4 bi = sbox[kslot[cb + i]];
                        float xx1 = fmaxf(bi.x, bj.x), yy1 = fmaxf(bi.y, bj.y);
                        float xx2 = fminf(bi.z, bj.z), yy2 = fminf(bi.w, bj.w);
                        float inter = fmaxf(xx2 - xx1, 0.f) * fmaxf(yy2 - yy1, 0.f);
                        float areai = (bi.z - bi.x) * (bi.w - bi.y);
                        float iou = inter / (areai + areaj - inter + 1e-6f);
                        if (iou > 0.5f)
                            atomicOr(&supmask[(j << 2) + (i >> 5)], 1u << (i & 31));
                    }
                }
            }
            __syncthreads();

            // serial bitmask walk (thread 0)
            if (tid == 0) {
                unsigned S0 = 0, S1 = 0, S2 = 0, S3 = 0;
                int ns2 = s_nsel;
                for (int c = 0; c < cl && ns2 < K_DET; ++c) {
                    if (presup[c]) continue;
                    unsigned hitm = (supmask[(c << 2) + 0] & S0) |
                                    (supmask[(c << 2) + 1] & S1) |
                                    (supmask[(c << 2) + 2] & S2) |
                                    (supmask[(c << 2) + 3] & S3);
                    if (hitm) continue;
                    int sl = kslot[cb + c];
                    selbox[ns2] = sbox[sl];
                    selsc[ns2]  = ssc[sl];
                    seloi[ns2]  = soi[sl];
                    ns2++;
                    if (c < 32)       S0 |= 1u << c;
                    else if (c < 64)  S1 |= 1u << (c - 32);
                    else if (c < 96)  S2 |= 1u << (c - 64);
                    else              S3 |= 1u << (c - 96);
                }
                s_nsel = ns2;
            }
            __syncthreads();
            if (s_nsel >= K_DET) break;
        }
        if (s_nsel >= K_DET) break;
    }
    __syncthreads();

    // ---- Phase 5: outputs (idx | scores | boxes | classes | num_valid) ----
    const int nsel = s_nsel;
    const int* cls_in = classes + (size_t)img * N;
    const size_t BK = (size_t)B * K_DET;
    for (int t = tid; t < K_DET; t += NTHREADS) {
        size_t r = (size_t)img * K_DET + t;
        if (t < nsel) {
            int oi = seloi[t];
            out[r]      = (float)oi;
            out[BK + r] = selsc[t];
            float4 b4 = selbox[t];
            out[2 * BK + 4 * r + 0] = b4.x;
            out[2 * BK + 4 * r + 1] = b4.y;
            out[2 * BK + 4 * r + 2] = b4.z;
            out[2 * BK + 4 * r + 3] = b4.w;
            out[6 * BK + r] = (float)cls_in[oi];
        } else {
            out[r]      = -1.f;
            out[BK + r] = 0.f;
            out[2 * BK + 4 * r + 0] = 0.f;
            out[2 * BK + 4 * r + 1] = 0.f;
            out[2 * BK + 4 * r + 2] = 0.f;
            out[2 * BK + 4 * r + 3] = 0.f;
            out[6 * BK + r] = -1.f;
        }
    }
    if (tid == 0) out[7 * BK + img] = (float)nsel;
}

extern "C" void kernel_launch(void* const* d_in, const int* in_sizes, int n_in,
                              void* d_out, int out_size) {
    const float* scores  = (const float*)d_in[0];
    const float* boxes   = (const float*)d_in[1];
    const int*   classes = (const int*)d_in[2];
    float* out = (float*)d_out;

    int B = out_size / (7 * K_DET + 1);
    if (B < 1) B = 1;
    int N = in_sizes[0] / B;

    size_t smem = (size_t)CAP * 16          // sbox
                + (size_t)K_DET * 16        // selbox
                + (size_t)SORT_MAX * 8      // skey
                + (size_t)CAP * 4 * 2       // ssc, soi
                + (size_t)SORT_MAX * 4      // kslot
                + (size_t)NBINS * 4 * 3     // hist, binstart, binpos
                + (size_t)K_DET * 4 * 2     // selsc, seloi
                + (size_t)CHUNK * 4         // presup
                + (size_t)CHUNK * 16;       // supmask

    cudaFuncSetAttribute(nms_kernel,
                         cudaFuncAttributeMaxDynamicSharedMemorySize,
                         (int)smem);

    nms_kernel<<<B, NTHREADS, smem>>>(scores, boxes, classes, out, B, N);
}